// round 5
// baseline (speedup 1.0000x reference)
#include <cuda_runtime.h>
#include <math.h>
#include <stdint.h>

// ---------------- problem constants ----------------
#define Mn    200
#define Sn    20
#define Hn    3
#define Cn    100
#define Ln    5
#define HIDn  150
#define Bn    128
#define En    3200
#define Kn    160
#define ETOT  3400          // E + M self loops
#define OBSD  9002
#define PASTD 277
#define HC    300           // H*C
#define D2IN  49600
#define GDIM  600           // 4*HID
#define SPLITK 62
#define CHUNKK 800          // 62*800 = 49600

// ---------------- scratch (device globals, allocation-free) ----------------
__device__ float g_xflat[1280 * PASTD];
__device__ float g_gx[1280 * GDIM];
__device__ float g_h[2 * Bn * HIDn];
__device__ float g_c[2 * Bn * HIDn];
__device__ float g_gates[2 * Bn * GDIM];
__device__ float g_feat[Bn * Mn * 42];
__device__ float g_xl[Bn * Mn * HC];
__device__ float g_xr[Bn * Mn * HC];
__device__ float g_gatout[Bn * Mn * HC];
__device__ float g_score[Bn * Mn];
__device__ int   g_coff[Mn + 1];
__device__ int   g_csrc[ETOT];
__device__ float g_concat[Bn * D2IN];
__device__ float g_partial[SPLITK * Bn * 128];
__device__ float g_hidden[Bn * 128];

// ---------------- helpers ----------------
__device__ __forceinline__ float sigf(float x) { return 1.0f / (1.0f + expf(-x)); }

// ---------------- generic tiled GEMM: C = act(A@B + bias1 + bias2) ----------------
// A: Mr x Kd (lda), B: Kd x N (ldb), C: Mr x N (ldc). act: 0 none, 1 ELU, 2 leaky(slope)
__global__ void gemm_bias_act(const float* __restrict__ A, int lda,
                              const float* __restrict__ B, int ldb,
                              float* __restrict__ C, int ldc,
                              const float* __restrict__ bias1,
                              const float* __restrict__ bias2,
                              int Mr, int N, int Kd, int act, float slope)
{
    __shared__ float As[16][68];
    __shared__ float Bs[16][64];
    const int tid = threadIdx.x;
    const int m0 = blockIdx.y * 64;
    const int n0 = blockIdx.x * 64;
    const int tx = tid & 15;
    const int ty = tid >> 4;
    float acc[4][4] = {};

    for (int k0 = 0; k0 < Kd; k0 += 16) {
        {
            int ka = k0 + tx;
            #pragma unroll
            for (int it = 0; it < 4; it++) {
                int m = ty + 16 * it;
                int gm = m0 + m;
                float v = 0.0f;
                if (gm < Mr && ka < Kd) v = A[(size_t)gm * lda + ka];
                As[tx][m] = v;
            }
        }
        {
            int c = tid & 63;
            int kb = tid >> 6;
            #pragma unroll
            for (int it = 0; it < 4; it++) {
                int kk = kb + 4 * it;
                int gk = k0 + kk;
                float v = 0.0f;
                if (gk < Kd && (n0 + c) < N) v = B[(size_t)gk * ldb + n0 + c];
                Bs[kk][c] = v;
            }
        }
        __syncthreads();
        #pragma unroll
        for (int k = 0; k < 16; k++) {
            float4 a = *(const float4*)&As[k][ty * 4];
            float4 b = *(const float4*)&Bs[k][tx * 4];
            acc[0][0] += a.x * b.x; acc[0][1] += a.x * b.y; acc[0][2] += a.x * b.z; acc[0][3] += a.x * b.w;
            acc[1][0] += a.y * b.x; acc[1][1] += a.y * b.y; acc[1][2] += a.y * b.z; acc[1][3] += a.y * b.w;
            acc[2][0] += a.z * b.x; acc[2][1] += a.z * b.y; acc[2][2] += a.z * b.z; acc[2][3] += a.z * b.w;
            acc[3][0] += a.w * b.x; acc[3][1] += a.w * b.y; acc[3][2] += a.w * b.z; acc[3][3] += a.w * b.w;
        }
        __syncthreads();
    }

    #pragma unroll
    for (int i = 0; i < 4; i++) {
        int row = m0 + ty * 4 + i;
        if (row >= Mr) continue;
        #pragma unroll
        for (int j = 0; j < 4; j++) {
            int col = n0 + tx * 4 + j;
            if (col >= N) continue;
            float v = acc[i][j];
            if (bias1) v += bias1[col];
            if (bias2) v += bias2[col];
            if (act == 1)      v = (v > 0.0f) ? v : (expf(v) - 1.0f);
            else if (act == 2) v = (v > 0.0f) ? v : slope * v;
            C[(size_t)row * ldc + col] = v;
        }
    }
}

// ---- dual-output variant: z=0 -> (B0,bias0,C0), z=1 -> (B1,bias1,C1); same A ----
__global__ void gemm_dual(const float* __restrict__ A, int lda,
                          const float* __restrict__ B0, const float* __restrict__ B1,
                          int ldb,
                          float* __restrict__ C0, float* __restrict__ C1, int ldc,
                          const float* __restrict__ bias0,
                          const float* __restrict__ bias1,
                          int Mr, int N, int Kd)
{
    __shared__ float As[16][68];
    __shared__ float Bs[16][64];
    const int tid = threadIdx.x;
    const int m0 = blockIdx.y * 64;
    const int n0 = blockIdx.x * 64;
    const float* __restrict__ B = blockIdx.z ? B1 : B0;
    float* __restrict__ C = blockIdx.z ? C1 : C0;
    const float* __restrict__ bias = blockIdx.z ? bias1 : bias0;
    const int tx = tid & 15;
    const int ty = tid >> 4;
    float acc[4][4] = {};

    for (int k0 = 0; k0 < Kd; k0 += 16) {
        {
            int ka = k0 + tx;
            #pragma unroll
            for (int it = 0; it < 4; it++) {
                int m = ty + 16 * it;
                int gm = m0 + m;
                float v = 0.0f;
                if (gm < Mr && ka < Kd) v = A[(size_t)gm * lda + ka];
                As[tx][m] = v;
            }
        }
        {
            int c = tid & 63;
            int kb = tid >> 6;
            #pragma unroll
            for (int it = 0; it < 4; it++) {
                int kk = kb + 4 * it;
                int gk = k0 + kk;
                float v = 0.0f;
                if (gk < Kd && (n0 + c) < N) v = B[(size_t)gk * ldb + n0 + c];
                Bs[kk][c] = v;
            }
        }
        __syncthreads();
        #pragma unroll
        for (int k = 0; k < 16; k++) {
            float4 a = *(const float4*)&As[k][ty * 4];
            float4 b = *(const float4*)&Bs[k][tx * 4];
            acc[0][0] += a.x * b.x; acc[0][1] += a.x * b.y; acc[0][2] += a.x * b.z; acc[0][3] += a.x * b.w;
            acc[1][0] += a.y * b.x; acc[1][1] += a.y * b.y; acc[1][2] += a.y * b.z; acc[1][3] += a.y * b.w;
            acc[2][0] += a.z * b.x; acc[2][1] += a.z * b.y; acc[2][2] += a.z * b.z; acc[2][3] += a.z * b.w;
            acc[3][0] += a.w * b.x; acc[3][1] += a.w * b.y; acc[3][2] += a.w * b.z; acc[3][3] += a.w * b.w;
        }
        __syncthreads();
    }

    #pragma unroll
    for (int i = 0; i < 4; i++) {
        int row = m0 + ty * 4 + i;
        if (row >= Mr) continue;
        #pragma unroll
        for (int j = 0; j < 4; j++) {
            int col = n0 + tx * 4 + j;
            if (col >= N) continue;
            C[(size_t)row * ldc + col] = acc[i][j] + bias[col];
        }
    }
}

// ---------------- split-K GEMM writing partials (deterministic, no atomics) ----------------
__global__ void gemm_splitk(const float* __restrict__ A, int lda,
                            const float* __restrict__ B, int ldb,
                            int Mr, int N, int Kd)
{
    __shared__ float As[16][68];
    __shared__ float Bs[16][64];
    const int tid = threadIdx.x;
    const int m0 = blockIdx.y * 64;
    const int n0 = blockIdx.x * 64;
    const int z  = blockIdx.z;
    const int kbeg = z * CHUNKK;
    const int kend = min(kbeg + CHUNKK, Kd);
    const int tx = tid & 15;
    const int ty = tid >> 4;
    float acc[4][4] = {};

    for (int k0 = kbeg; k0 < kend; k0 += 16) {
        {
            int ka = k0 + tx;
            #pragma unroll
            for (int it = 0; it < 4; it++) {
                int m = ty + 16 * it;
                int gm = m0 + m;
                float v = 0.0f;
                if (gm < Mr && ka < kend) v = A[(size_t)gm * lda + ka];
                As[tx][m] = v;
            }
        }
        {
            int c = tid & 63;
            int kb = tid >> 6;
            #pragma unroll
            for (int it = 0; it < 4; it++) {
                int kk = kb + 4 * it;
                int gk = k0 + kk;
                float v = 0.0f;
                if (gk < kend && (n0 + c) < N) v = __ldg(&B[(size_t)gk * ldb + n0 + c]);
                Bs[kk][c] = v;
            }
        }
        __syncthreads();
        #pragma unroll
        for (int k = 0; k < 16; k++) {
            float4 a = *(const float4*)&As[k][ty * 4];
            float4 b = *(const float4*)&Bs[k][tx * 4];
            acc[0][0] += a.x * b.x; acc[0][1] += a.x * b.y; acc[0][2] += a.x * b.z; acc[0][3] += a.x * b.w;
            acc[1][0] += a.y * b.x; acc[1][1] += a.y * b.y; acc[1][2] += a.y * b.z; acc[1][3] += a.y * b.w;
            acc[2][0] += a.z * b.x; acc[2][1] += a.z * b.y; acc[2][2] += a.z * b.z; acc[2][3] += a.z * b.w;
            acc[3][0] += a.w * b.x; acc[3][1] += a.w * b.y; acc[3][2] += a.w * b.z; acc[3][3] += a.w * b.w;
        }
        __syncthreads();
    }

    float* P = g_partial + (size_t)z * (Bn * 128);
    #pragma unroll
    for (int i = 0; i < 4; i++) {
        int row = m0 + ty * 4 + i;
        if (row >= Mr) continue;
        #pragma unroll
        for (int j = 0; j < 4; j++) {
            int col = n0 + tx * 4 + j;
            if (col >= N) continue;
            P[row * 128 + col] = acc[i][j];
        }
    }
}

__global__ void k_d2_reduce_act(const float* __restrict__ d2_b)
{
    int idx = blockIdx.x * 256 + threadIdx.x;
    if (idx >= Bn * 128) return;
    float s = 0.0f;
    #pragma unroll 4
    for (int z = 0; z < SPLITK; z++) s += g_partial[z * (Bn * 128) + idx];
    s += d2_b[idx & 127];
    g_hidden[idx] = (s > 0.0f) ? s : (expf(s) - 1.0f);
}

// ---------------- LSTM ----------------
__global__ void k_xflat(const float* __restrict__ past)
{
    int idx = blockIdx.x * 256 + threadIdx.x;
    if (idx >= 1280 * PASTD) return;
    int r = idx / PASTD, k = idx % PASTD;
    int dir = r / 640;
    int rr = r % 640;
    int t = rr / Bn, b = rr % Bn;
    int teff = dir ? (Ln - 1 - t) : t;
    g_xflat[idx] = past[(b * Ln + teff) * PASTD + k];
}

__global__ void k_gates(const float* __restrict__ whh_f,
                        const float* __restrict__ whh_b, int step)
{
    const int chunk = blockIdx.x;          // 0..9 (64 cols each)
    const int b0 = blockIdx.y * 32;
    const int dir = blockIdx.z;
    const float* __restrict__ whh = dir ? whh_b : whh_f;
    __shared__ float h_sh[32][HIDn];
    int tid = threadIdx.x;
    for (int i = tid; i < 32 * HIDn; i += 256) {
        int bb = i / HIDn, u = i % HIDn;
        h_sh[bb][u] = (step == 0) ? 0.0f : g_h[(dir * Bn + b0 + bb) * HIDn + u];
    }
    __syncthreads();
    int col = chunk * 64 + (tid & 63);
    int bi = tid >> 6;                     // 0..3
    if (col >= GDIM) return;
    float acc[8] = {};
    for (int k = 0; k < HIDn; k++) {
        float wv = whh[k * GDIM + col];
        #pragma unroll
        for (int i = 0; i < 8; i++) acc[i] += h_sh[bi + 4 * i][k] * wv;
    }
    #pragma unroll
    for (int i = 0; i < 8; i++) {
        int b = b0 + bi + 4 * i;
        g_gates[(dir * Bn + b) * GDIM + col] =
            g_gx[(((dir * Ln + step) * Bn) + b) * GDIM + col] + acc[i];
    }
}

__global__ void k_lstm_update(int step)
{
    int idx = blockIdx.x * 256 + threadIdx.x;
    if (idx >= 2 * Bn * HIDn) return;
    int dir = idx / (Bn * HIDn);
    int r = idx % (Bn * HIDn);
    int b = r / HIDn, u = r % HIDn;
    const float* g = &g_gates[(dir * Bn + b) * GDIM];
    float iv = sigf(g[u]);
    float fv = sigf(g[HIDn + u]);
    float gv = tanhf(g[2 * HIDn + u]);
    float ov = sigf(g[3 * HIDn + u]);
    float c = (step == 0) ? 0.0f : g_c[idx];
    c = fv * c + iv * gv;
    float h = ov * tanhf(c);
    g_c[idx] = c;
    g_h[idx] = h;
    int tout = dir ? (Ln - 1 - step) : step;
    g_concat[b * D2IN + 48100 + tout * HC + dir * HIDn + u] = h;
}

// ---------------- GAT ----------------
__global__ void k_feat(const float* __restrict__ obs)
{
    int idx = blockIdx.x * 256 + threadIdx.x;
    if (idx >= Bn * Mn * 42) return;
    int b = idx / (Mn * 42);
    int r = idx % (Mn * 42);
    int m = r / 42, j = r % 42;
    const float* o = obs + (size_t)b * OBSD;
    float v;
    if (j == 0)       v = o[3 * Mn + 2 + m];
    else if (j == 1)  v = o[4 * Mn + 2 + m];
    else if (j < 22)  v = o[5 * Mn + 2 + m * Sn + (j - 2)];
    else              v = o[5 * Mn + 2 + Mn * Sn + m * Sn + (j - 22)];
    g_feat[idx] = v;
}

__global__ void k_csr_count(const int* __restrict__ EI)
{
    __shared__ int cnt[Mn];
    int tid = threadIdx.x;
    for (int i = tid; i < Mn; i += 256) cnt[i] = 0;
    __syncthreads();
    for (int e = tid; e < ETOT; e += 256) {
        int tgt = (e < En) ? EI[En + e] : (e - En);
        atomicAdd(&cnt[tgt], 1);
    }
    __syncthreads();
    if (tid == 0) {
        int run = 0;
        for (int m = 0; m < Mn; m++) { g_coff[m] = run; run += cnt[m]; }
        g_coff[Mn] = run;
    }
}

// deterministic stable CSR scatter by rank counting
__global__ void k_csr_scatter(const int* __restrict__ EI)
{
    __shared__ int tg_sh[ETOT];
    int tid = threadIdx.x;
    for (int i = tid; i < ETOT; i += 256)
        tg_sh[i] = (i < En) ? EI[En + i] : (i - En);
    __syncthreads();
    int e = blockIdx.x * 256 + tid;
    if (e >= ETOT) return;
    int tgt = tg_sh[e];
    int rank = 0;
    for (int j = 0; j < e; j++) rank += (tg_sh[j] == tgt);
    int slot = g_coff[tgt] + rank;
    g_csrc[slot] = (e < En) ? EI[e] : (e - En);
}

// Fused GAT attention: logits + segment softmax (online) + aggregation.
// One block per (b, h). xl[b,:,h,:] staged in 80KB dynamic smem; per-warp
// per-target accumulation in registers. Deterministic (CSR order, no atomics).
__global__ void k_gat_fused(const float* __restrict__ att,
                            const float* __restrict__ gat_bias)
{
    extern __shared__ float xl_sh[];   // Mn*Cn = 20000 floats = 80KB
    __shared__ float seg_lg[8][64];
    int b = blockIdx.x, h = blockIdx.y;
    int tid = threadIdx.x;
    for (int i = tid; i < Mn * Cn; i += 256) {
        int m = i / Cn, c = i % Cn;
        xl_sh[i] = g_xl[((size_t)b * Mn + m) * HC + h * Cn + c];
    }
    __syncthreads();
    int w = tid >> 5, lane = tid & 31;
    float attc0 = att[h * Cn + lane];
    float attc1 = att[h * Cn + lane + 32];
    float attc2 = att[h * Cn + lane + 64];
    float attc3 = (lane < 4) ? att[h * Cn + lane + 96] : 0.0f;
    float bi0 = gat_bias[h * Cn + lane];
    float bi1 = gat_bias[h * Cn + lane + 32];
    float bi2 = gat_bias[h * Cn + lane + 64];
    float bi3 = (lane < 4) ? gat_bias[h * Cn + lane + 96] : 0.0f;

    for (int t = w; t < Mn; t += 8) {
        const float* xrr = g_xr + ((size_t)b * Mn + t) * HC + h * Cn;
        float xr0 = xrr[lane], xr1 = xrr[lane + 32], xr2 = xrr[lane + 64];
        float xr3 = (lane < 4) ? xrr[lane + 96] : 0.0f;
        int s0 = g_coff[t], s1 = g_coff[t + 1];
        int len = s1 - s0;
        float mx = -1e30f, den = 0.0f;
        for (int jj = 0; jj < len; jj++) {
            int src = g_csrc[s0 + jj];
            const float* x = &xl_sh[src * Cn];
            float v0 = x[lane] + xr0;       v0 = (v0 > 0.f) ? v0 : 0.2f * v0;
            float v1 = x[lane + 32] + xr1;  v1 = (v1 > 0.f) ? v1 : 0.2f * v1;
            float v2 = x[lane + 64] + xr2;  v2 = (v2 > 0.f) ? v2 : 0.2f * v2;
            float s = v0 * attc0 + v1 * attc1 + v2 * attc2;
            if (lane < 4) {
                float v3 = x[lane + 96] + xr3; v3 = (v3 > 0.f) ? v3 : 0.2f * v3;
                s += v3 * attc3;
            }
            #pragma unroll
            for (int o = 16; o; o >>= 1) s += __shfl_xor_sync(0xffffffffu, s, o);
            if (jj < 64 && lane == 0) seg_lg[w][jj] = s;
            if (s > mx) { den = den * expf(mx - s) + 1.0f; mx = s; }
            else        den += expf(s - mx);
        }
        __syncwarp();
        float inv = 1.0f / den;
        float a0 = 0, a1 = 0, a2 = 0, a3 = 0;
        for (int jj = 0; jj < len; jj++) {
            int src = g_csrc[s0 + jj];
            const float* x = &xl_sh[src * Cn];
            float lg;
            if (jj < 64) lg = seg_lg[w][jj];
            else {
                float v0 = x[lane] + xr0;       v0 = (v0 > 0.f) ? v0 : 0.2f * v0;
                float v1 = x[lane + 32] + xr1;  v1 = (v1 > 0.f) ? v1 : 0.2f * v1;
                float v2 = x[lane + 64] + xr2;  v2 = (v2 > 0.f) ? v2 : 0.2f * v2;
                float s = v0 * attc0 + v1 * attc1 + v2 * attc2;
                if (lane < 4) {
                    float v3 = x[lane + 96] + xr3; v3 = (v3 > 0.f) ? v3 : 0.2f * v3;
                    s += v3 * attc3;
                }
                #pragma unroll
                for (int o = 16; o; o >>= 1) s += __shfl_xor_sync(0xffffffffu, s, o);
                lg = s;
            }
            float al = expf(lg - mx) * inv;
            a0 += al * x[lane];
            a1 += al * x[lane + 32];
            a2 += al * x[lane + 64];
            if (lane < 4) a3 += al * x[lane + 96];
        }
        float* orow = g_gatout + ((size_t)b * Mn + t) * HC + h * Cn;
        orow[lane]      = a0 + bi0;
        orow[lane + 32] = a1 + bi1;
        orow[lane + 64] = a2 + bi2;
        if (lane < 4) orow[lane + 96] = a3 + bi3;
    }
}

// score[b][m] = tanh(gat_out[b,m,:]·pool_w / ||pool_w||)
__global__ void k_score(const float* __restrict__ pool_w)
{
    int gw = blockIdx.x * 8 + (threadIdx.x >> 5);
    int lane = threadIdx.x & 31;
    if (gw >= Bn * Mn) return;
    int b = gw / Mn, m = gw % Mn;
    const float* row = g_gatout + ((size_t)b * Mn + m) * HC;
    float nw = 0.0f, dt = 0.0f;
    for (int c = lane; c < HC; c += 32) {
        float w = pool_w[c];
        nw += w * w;
        dt += w * row[c];
    }
    #pragma unroll
    for (int o = 16; o; o >>= 1) {
        nw += __shfl_xor_sync(0xffffffffu, nw, o);
        dt += __shfl_xor_sync(0xffffffffu, dt, o);
    }
    if (lane == 0) g_score[b * Mn + m] = tanhf(dt / sqrtf(nw));
}

// top-k (K=160 of 200) by stable rank counting; write pooled into concat
__global__ void k_topk_pool()
{
    __shared__ float s_sh[Mn];
    __shared__ int   sel_idx[Kn];
    __shared__ float sel_val[Kn];
    int b = blockIdx.x;
    int tid = threadIdx.x;
    for (int i = tid; i < Mn; i += 256) s_sh[i] = g_score[b * Mn + i];
    __syncthreads();
    if (tid < Mn) {
        float sv = s_sh[tid];
        int rank = 0;
        for (int j = 0; j < Mn; j++) {
            float o = s_sh[j];
            rank += (o > sv) || (o == sv && j < tid);
        }
        if (rank < Kn) { sel_idx[rank] = tid; sel_val[rank] = sv; }
    }
    __syncthreads();
    for (int idx = tid; idx < Kn * HC; idx += 256) {
        int r = idx / HC, c = idx % HC;
        g_concat[b * D2IN + 100 + idx] =
            g_gatout[((size_t)b * Mn + sel_idx[r]) * HC + c] * sel_val[r];
    }
}

// ---------------- launch ----------------
extern "C" void kernel_launch(void* const* d_in, const int* in_sizes, int n_in,
                              void* d_out, int out_size)
{
    const float* obs    = (const float*)d_in[0];
    const float* past   = (const float*)d_in[1];
    const int*   ei     = (const int*)d_in[2];
    const float* d1_w   = (const float*)d_in[3];
    const float* d1_b   = (const float*)d_in[4];
    const float* d2_w   = (const float*)d_in[5];
    const float* d2_b   = (const float*)d_in[6];
    const float* gat_wl = (const float*)d_in[7];
    const float* gat_bl = (const float*)d_in[8];
    const float* gat_wr = (const float*)d_in[9];
    const float* gat_br = (const float*)d_in[10];
    const float* gat_att  = (const float*)d_in[11];
    const float* gat_bias = (const float*)d_in[12];
    const float* pool_w   = (const float*)d_in[13];
    const float* wih_f  = (const float*)d_in[14];
    const float* whh_f  = (const float*)d_in[15];
    const float* bih_f  = (const float*)d_in[16];
    const float* bhh_f  = (const float*)d_in[17];
    const float* wih_b  = (const float*)d_in[18];
    const float* whh_b  = (const float*)d_in[19];
    const float* bih_b  = (const float*)d_in[20];
    const float* bhh_b  = (const float*)d_in[21];
    const float* out_w  = (const float*)d_in[22];
    const float* out_b  = (const float*)d_in[23];
    float* out = (float*)d_out;

    float *p_xflat, *p_gx, *p_feat, *p_xl, *p_xr, *p_concat, *p_hidden;
    cudaGetSymbolAddress((void**)&p_xflat,  g_xflat);
    cudaGetSymbolAddress((void**)&p_gx,     g_gx);
    cudaGetSymbolAddress((void**)&p_feat,   g_feat);
    cudaGetSymbolAddress((void**)&p_xl,     g_xl);
    cudaGetSymbolAddress((void**)&p_xr,     g_xr);
    cudaGetSymbolAddress((void**)&p_concat, g_concat);
    cudaGetSymbolAddress((void**)&p_hidden, g_hidden);

    cudaFuncSetAttribute(k_gat_fused, cudaFuncAttributeMaxDynamicSharedMemorySize,
                         Mn * Cn * 4);

    // ---- LSTM input projection ----
    k_xflat<<<(1280 * PASTD + 255) / 256, 256>>>(past);
    gemm_bias_act<<<dim3(10, 10), 256>>>(p_xflat, PASTD, wih_f, GDIM,
                                         p_gx, GDIM, bih_f, bhh_f,
                                         640, GDIM, PASTD, 0, 0.0f);
    gemm_bias_act<<<dim3(10, 10), 256>>>(p_xflat + 640 * PASTD, PASTD, wih_b, GDIM,
                                         p_gx + 640 * GDIM, GDIM, bih_b, bhh_b,
                                         640, GDIM, PASTD, 0, 0.0f);

    // ---- GAT feature + fused xl/xr projections ----
    k_feat<<<(Bn * Mn * 42 + 255) / 256, 256>>>(obs);
    gemm_dual<<<dim3(5, 400, 2), 256>>>(p_feat, 42, gat_wl, gat_wr, HC,
                                        p_xl, p_xr, HC, gat_bl, gat_br,
                                        Bn * Mn, HC, 42);

    // ---- CSR build (deterministic) ----
    k_csr_count<<<1, 256>>>(ei);
    k_csr_scatter<<<(ETOT + 255) / 256, 256>>>(ei);

    // ---- fused GAT attention (logits + softmax + aggregate) ----
    k_gat_fused<<<dim3(Bn, Hn), 256, Mn * Cn * 4>>>(gat_att, gat_bias);

    // ---- pooling ----
    k_score<<<(Bn * Mn + 7) / 8, 256>>>(pool_w);
    k_topk_pool<<<Bn, 256>>>();

    // ---- LSTM recurrence (writes past_enc into concat) ----
    for (int s = 0; s < Ln; s++) {
        k_gates<<<dim3(10, 4, 2), 256>>>(whh_f, whh_b, s);
        k_lstm_update<<<(2 * Bn * HIDn + 255) / 256, 256>>>(s);
    }

    // ---- d1 -> concat[:, 0:100] ----
    gemm_bias_act<<<dim3(2, 2), 256>>>(obs, OBSD, d1_w, 100,
                                       p_concat, D2IN, d1_b, nullptr,
                                       Bn, 100, 3 * Mn + 2, 1, 0.0f);

    // ---- d2 split-K GEMM + reduce/ELU ----
    gemm_splitk<<<dim3(2, 2, SPLITK), 256>>>(p_concat, D2IN, d2_w, 128,
                                             Bn, 128, D2IN);
    k_d2_reduce_act<<<(Bn * 128 + 255) / 256, 256>>>(d2_b);

    // ---- output layer ----
    gemm_bias_act<<<dim3(4, 2), 256>>>(p_hidden, 128, out_w, Mn,
                                       out, Mn, out_b, nullptr,
                                       Bn, Mn, 128, 2, 0.01f);
}

// round 7
// speedup vs baseline: 1.2092x; 1.2092x over previous
#include <cuda_runtime.h>
#include <math.h>
#include <stdint.h>

// ---------------- problem constants ----------------
#define Mn    200
#define Sn    20
#define Hn    3
#define Cn    100
#define Ln    5
#define HIDn  150
#define Bn    128
#define En    3200
#define Kn    160
#define ETOT  3400          // E + M self loops
#define OBSD  9002
#define PASTD 277
#define HC    300           // H*C
#define D2IN  49600
#define GDIM  600           // 4*HID
#define SPLITK 148
#define CHUNKK 336          // 148*336 = 49728 >= 49600

// ---------------- scratch (device globals, allocation-free) ----------------
__device__ float g_xflat[1280 * PASTD];
__device__ float g_gx[1280 * GDIM];
__device__ float g_h[2 * Bn * HIDn];
__device__ float g_c[2 * Bn * HIDn];
__device__ float g_gates[2 * Bn * GDIM];
__device__ float g_feat[Bn * Mn * 42];
__device__ float g_xl[Bn * Mn * HC];
__device__ float g_xr[Bn * Mn * HC];
__device__ float g_gatout[Bn * Mn * HC];
__device__ float g_score[Bn * Mn];
__device__ int   g_coff[Mn + 1];
__device__ int   g_csrc[ETOT];
__device__ float g_concat[Bn * D2IN];
__device__ float g_partial[SPLITK * 128 * 128];
__device__ float g_hidden[Bn * 128];

// ---------------- helpers ----------------
__device__ __forceinline__ float sigf(float x) { return 1.0f / (1.0f + expf(-x)); }

// ---------------- generic tiled GEMM: C = act(A@B + bias1 + bias2) ----------------
__global__ void gemm_bias_act(const float* __restrict__ A, int lda,
                              const float* __restrict__ B, int ldb,
                              float* __restrict__ C, int ldc,
                              const float* __restrict__ bias1,
                              const float* __restrict__ bias2,
                              int Mr, int N, int Kd, int act, float slope)
{
    __shared__ float As[16][68];
    __shared__ float Bs[16][64];
    const int tid = threadIdx.x;
    const int m0 = blockIdx.y * 64;
    const int n0 = blockIdx.x * 64;
    const int tx = tid & 15;
    const int ty = tid >> 4;
    float acc[4][4] = {};

    for (int k0 = 0; k0 < Kd; k0 += 16) {
        {
            int ka = k0 + tx;
            #pragma unroll
            for (int it = 0; it < 4; it++) {
                int m = ty + 16 * it;
                int gm = m0 + m;
                float v = 0.0f;
                if (gm < Mr && ka < Kd) v = A[(size_t)gm * lda + ka];
                As[tx][m] = v;
            }
        }
        {
            int c = tid & 63;
            int kb = tid >> 6;
            #pragma unroll
            for (int it = 0; it < 4; it++) {
                int kk = kb + 4 * it;
                int gk = k0 + kk;
                float v = 0.0f;
                if (gk < Kd && (n0 + c) < N) v = B[(size_t)gk * ldb + n0 + c];
                Bs[kk][c] = v;
            }
        }
        __syncthreads();
        #pragma unroll
        for (int k = 0; k < 16; k++) {
            float4 a = *(const float4*)&As[k][ty * 4];
            float4 b = *(const float4*)&Bs[k][tx * 4];
            acc[0][0] += a.x * b.x; acc[0][1] += a.x * b.y; acc[0][2] += a.x * b.z; acc[0][3] += a.x * b.w;
            acc[1][0] += a.y * b.x; acc[1][1] += a.y * b.y; acc[1][2] += a.y * b.z; acc[1][3] += a.y * b.w;
            acc[2][0] += a.z * b.x; acc[2][1] += a.z * b.y; acc[2][2] += a.z * b.z; acc[2][3] += a.z * b.w;
            acc[3][0] += a.w * b.x; acc[3][1] += a.w * b.y; acc[3][2] += a.w * b.z; acc[3][3] += a.w * b.w;
        }
        __syncthreads();
    }

    #pragma unroll
    for (int i = 0; i < 4; i++) {
        int row = m0 + ty * 4 + i;
        if (row >= Mr) continue;
        #pragma unroll
        for (int j = 0; j < 4; j++) {
            int col = n0 + tx * 4 + j;
            if (col >= N) continue;
            float v = acc[i][j];
            if (bias1) v += bias1[col];
            if (bias2) v += bias2[col];
            if (act == 1)      v = (v > 0.0f) ? v : (expf(v) - 1.0f);
            else if (act == 2) v = (v > 0.0f) ? v : slope * v;
            C[(size_t)row * ldc + col] = v;
        }
    }
}

// ---- dual-output variant: z=0 -> (B0,bias0,C0), z=1 -> (B1,bias1,C1); same A ----
__global__ void gemm_dual(const float* __restrict__ A, int lda,
                          const float* __restrict__ B0, const float* __restrict__ B1,
                          int ldb,
                          float* __restrict__ C0, float* __restrict__ C1, int ldc,
                          const float* __restrict__ bias0,
                          const float* __restrict__ bias1,
                          int Mr, int N, int Kd)
{
    __shared__ float As[16][68];
    __shared__ float Bs[16][64];
    const int tid = threadIdx.x;
    const int m0 = blockIdx.y * 64;
    const int n0 = blockIdx.x * 64;
    const float* __restrict__ B = blockIdx.z ? B1 : B0;
    float* __restrict__ C = blockIdx.z ? C1 : C0;
    const float* __restrict__ bias = blockIdx.z ? bias1 : bias0;
    const int tx = tid & 15;
    const int ty = tid >> 4;
    float acc[4][4] = {};

    for (int k0 = 0; k0 < Kd; k0 += 16) {
        {
            int ka = k0 + tx;
            #pragma unroll
            for (int it = 0; it < 4; it++) {
                int m = ty + 16 * it;
                int gm = m0 + m;
                float v = 0.0f;
                if (gm < Mr && ka < Kd) v = A[(size_t)gm * lda + ka];
                As[tx][m] = v;
            }
        }
        {
            int c = tid & 63;
            int kb = tid >> 6;
            #pragma unroll
            for (int it = 0; it < 4; it++) {
                int kk = kb + 4 * it;
                int gk = k0 + kk;
                float v = 0.0f;
                if (gk < Kd && (n0 + c) < N) v = B[(size_t)gk * ldb + n0 + c];
                Bs[kk][c] = v;
            }
        }
        __syncthreads();
        #pragma unroll
        for (int k = 0; k < 16; k++) {
            float4 a = *(const float4*)&As[k][ty * 4];
            float4 b = *(const float4*)&Bs[k][tx * 4];
            acc[0][0] += a.x * b.x; acc[0][1] += a.x * b.y; acc[0][2] += a.x * b.z; acc[0][3] += a.x * b.w;
            acc[1][0] += a.y * b.x; acc[1][1] += a.y * b.y; acc[1][2] += a.y * b.z; acc[1][3] += a.y * b.w;
            acc[2][0] += a.z * b.x; acc[2][1] += a.z * b.y; acc[2][2] += a.z * b.z; acc[2][3] += a.z * b.w;
            acc[3][0] += a.w * b.x; acc[3][1] += a.w * b.y; acc[3][2] += a.w * b.z; acc[3][3] += a.w * b.w;
        }
        __syncthreads();
    }

    #pragma unroll
    for (int i = 0; i < 4; i++) {
        int row = m0 + ty * 4 + i;
        if (row >= Mr) continue;
        #pragma unroll
        for (int j = 0; j < 4; j++) {
            int col = n0 + tx * 4 + j;
            if (col >= N) continue;
            C[(size_t)row * ldc + col] = acc[i][j] + bias[col];
        }
    }
}

// ---------------- split-K d2 GEMM: one 128x128 block per K-chunk ----------------
// A = g_concat (128 x 49600), B = d2_w (49600 x 128). Deterministic partials.
__global__ __launch_bounds__(256) void gemm_splitk(const float* __restrict__ A,
                                                   const float* __restrict__ B)
{
    __shared__ float As[16][132];
    __shared__ float Bs[16][132];
    const int tid = threadIdx.x;
    const int z = blockIdx.x;
    const int kbeg = z * CHUNKK;
    const int kend = min(kbeg + CHUNKK, D2IN);
    const int tx = tid & 15, ty = tid >> 4;
    float acc[8][8] = {};

    for (int k0 = kbeg; k0 < kend; k0 += 16) {
        #pragma unroll
        for (int i = 0; i < 8; i++) {          // A: 128 rows x 16 k
            int idx = tid + 256 * i;           // 0..2047
            int r = idx >> 4, kk = idx & 15;
            int gk = k0 + kk;
            As[kk][r] = (gk < kend) ? A[(size_t)r * D2IN + gk] : 0.0f;
        }
        #pragma unroll
        for (int i = 0; i < 8; i++) {          // B: 16 k x 128 cols
            int idx = tid + 256 * i;
            int c = idx & 127, kk = idx >> 7;
            int gk = k0 + kk;
            Bs[kk][c] = (gk < kend) ? B[(size_t)gk * 128 + c] : 0.0f;
        }
        __syncthreads();
        #pragma unroll
        for (int k = 0; k < 16; k++) {
            float4 a0 = *(const float4*)&As[k][ty * 8];
            float4 a1 = *(const float4*)&As[k][ty * 8 + 4];
            float4 b0 = *(const float4*)&Bs[k][tx * 8];
            float4 b1 = *(const float4*)&Bs[k][tx * 8 + 4];
            float av[8] = {a0.x, a0.y, a0.z, a0.w, a1.x, a1.y, a1.z, a1.w};
            float bv[8] = {b0.x, b0.y, b0.z, b0.w, b1.x, b1.y, b1.z, b1.w};
            #pragma unroll
            for (int i = 0; i < 8; i++)
                #pragma unroll
                for (int j = 0; j < 8; j++)
                    acc[i][j] += av[i] * bv[j];
        }
        __syncthreads();
    }

    float* P = g_partial + (size_t)z * (128 * 128);
    #pragma unroll
    for (int i = 0; i < 8; i++)
        #pragma unroll
        for (int j = 0; j < 8; j++)
            P[(ty * 8 + i) * 128 + tx * 8 + j] = acc[i][j];
}

__global__ void k_d2_reduce_act(const float* __restrict__ d2_b)
{
    int idx = blockIdx.x * 256 + threadIdx.x;
    if (idx >= Bn * 128) return;
    float s = 0.0f;
    #pragma unroll 4
    for (int z = 0; z < SPLITK; z++) s += g_partial[z * (128 * 128) + idx];
    s += d2_b[idx & 127];
    g_hidden[idx] = (s > 0.0f) ? s : (expf(s) - 1.0f);
}

// ---------------- LSTM ----------------
__global__ void k_xflat(const float* __restrict__ past)
{
    int idx = blockIdx.x * 256 + threadIdx.x;
    if (idx >= 1280 * PASTD) return;
    int r = idx / PASTD, k = idx % PASTD;
    int dir = r / 640;
    int rr = r % 640;
    int t = rr / Bn, b = rr % Bn;
    int teff = dir ? (Ln - 1 - t) : t;
    g_xflat[idx] = past[(b * Ln + teff) * PASTD + k];
}

__global__ void k_gates(const float* __restrict__ whh_f,
                        const float* __restrict__ whh_b, int step)
{
    const int chunk = blockIdx.x;          // 0..9 (64 cols each)
    const int b0 = blockIdx.y * 32;
    const int dir = blockIdx.z;
    const float* __restrict__ whh = dir ? whh_b : whh_f;
    __shared__ float h_sh[32][HIDn];
    int tid = threadIdx.x;
    for (int i = tid; i < 32 * HIDn; i += 256) {
        int bb = i / HIDn, u = i % HIDn;
        h_sh[bb][u] = (step == 0) ? 0.0f : g_h[(dir * Bn + b0 + bb) * HIDn + u];
    }
    __syncthreads();
    int col = chunk * 64 + (tid & 63);
    int bi = tid >> 6;                     // 0..3
    if (col >= GDIM) return;
    float acc[8] = {};
    for (int k = 0; k < HIDn; k++) {
        float wv = whh[k * GDIM + col];
        #pragma unroll
        for (int i = 0; i < 8; i++) acc[i] += h_sh[bi + 4 * i][k] * wv;
    }
    #pragma unroll
    for (int i = 0; i < 8; i++) {
        int b = b0 + bi + 4 * i;
        g_gates[(dir * Bn + b) * GDIM + col] =
            g_gx[(((dir * Ln + step) * Bn) + b) * GDIM + col] + acc[i];
    }
}

__global__ void k_lstm_update(int step)
{
    int idx = blockIdx.x * 256 + threadIdx.x;
    if (idx >= 2 * Bn * HIDn) return;
    int dir = idx / (Bn * HIDn);
    int r = idx % (Bn * HIDn);
    int b = r / HIDn, u = r % HIDn;
    const float* g = &g_gates[(dir * Bn + b) * GDIM];
    float iv = sigf(g[u]);
    float fv = sigf(g[HIDn + u]);
    float gv = tanhf(g[2 * HIDn + u]);
    float ov = sigf(g[3 * HIDn + u]);
    float c = (step == 0) ? 0.0f : g_c[idx];
    c = fv * c + iv * gv;
    float h = ov * tanhf(c);
    g_c[idx] = c;
    g_h[idx] = h;
    int tout = dir ? (Ln - 1 - step) : step;
    g_concat[b * D2IN + 48100 + tout * HC + dir * HIDn + u] = h;
}

// ---------------- GAT ----------------
__global__ void k_feat(const float* __restrict__ obs)
{
    int idx = blockIdx.x * 256 + threadIdx.x;
    if (idx >= Bn * Mn * 42) return;
    int b = idx / (Mn * 42);
    int r = idx % (Mn * 42);
    int m = r / 42, j = r % 42;
    const float* o = obs + (size_t)b * OBSD;
    float v;
    if (j == 0)       v = o[3 * Mn + 2 + m];
    else if (j == 1)  v = o[4 * Mn + 2 + m];
    else if (j < 22)  v = o[5 * Mn + 2 + m * Sn + (j - 2)];
    else              v = o[5 * Mn + 2 + Mn * Sn + m * Sn + (j - 22)];
    g_feat[idx] = v;
}

__global__ void k_csr_count(const int* __restrict__ EI)
{
    __shared__ int cnt[Mn];
    int tid = threadIdx.x;
    for (int i = tid; i < Mn; i += 256) cnt[i] = 0;
    __syncthreads();
    for (int e = tid; e < ETOT; e += 256) {
        int tgt = (e < En) ? EI[En + e] : (e - En);
        atomicAdd(&cnt[tgt], 1);
    }
    __syncthreads();
    if (tid == 0) {
        int run = 0;
        for (int m = 0; m < Mn; m++) { g_coff[m] = run; run += cnt[m]; }
        g_coff[Mn] = run;
    }
}

// deterministic stable CSR scatter by rank counting
__global__ void k_csr_scatter(const int* __restrict__ EI)
{
    __shared__ int tg_sh[ETOT];
    int tid = threadIdx.x;
    for (int i = tid; i < ETOT; i += 256)
        tg_sh[i] = (i < En) ? EI[En + i] : (i - En);
    __syncthreads();
    int e = blockIdx.x * 256 + tid;
    if (e >= ETOT) return;
    int tgt = tg_sh[e];
    int rank = 0;
    for (int j = 0; j < e; j++) rank += (tg_sh[j] == tgt);
    int slot = g_coff[tgt] + rank;
    g_csrc[slot] = (e < En) ? EI[e] : (e - En);
}

// Fused GAT attention v2: logits (2-edge ILP) -> smem logits -> lane-parallel
// softmax -> shuffle-free aggregation. One block per (b,h). Deterministic.
__global__ void k_gat_fused(const float* __restrict__ att,
                            const float* __restrict__ gat_bias)
{
    extern __shared__ float xl_sh[];   // Mn*Cn = 20000 floats = 80KB (dynamic)
    __shared__ float lg_sh[ETOT];      // 13.6KB static: per-slot logits -> alphas
    int b = blockIdx.x, h = blockIdx.y;
    int tid = threadIdx.x;
    for (int i = tid; i < Mn * Cn; i += 256) {
        int m = i / Cn, c = i % Cn;
        xl_sh[i] = g_xl[((size_t)b * Mn + m) * HC + h * Cn + c];
    }
    __syncthreads();
    int w = tid >> 5, lane = tid & 31;
    float attc0 = att[h * Cn + lane];
    float attc1 = att[h * Cn + lane + 32];
    float attc2 = att[h * Cn + lane + 64];
    float attc3 = (lane < 4) ? att[h * Cn + lane + 96] : 0.0f;
    float bi0 = gat_bias[h * Cn + lane];
    float bi1 = gat_bias[h * Cn + lane + 32];
    float bi2 = gat_bias[h * Cn + lane + 64];
    float bi3 = (lane < 4) ? gat_bias[h * Cn + lane + 96] : 0.0f;

    for (int t = w; t < Mn; t += 8) {
        const float* xrr = g_xr + ((size_t)b * Mn + t) * HC + h * Cn;
        float xr0 = xrr[lane], xr1 = xrr[lane + 32], xr2 = xrr[lane + 64];
        float xr3 = (lane < 4) ? xrr[lane + 96] : 0.0f;
        int s0 = g_coff[t], s1 = g_coff[t + 1];
        int len = s1 - s0;

        // ---- pass 1: logits into lg_sh, two edges in flight ----
        int jj = 0;
        for (; jj + 2 <= len; jj += 2) {
            int srcA = g_csrc[s0 + jj];
            int srcB = g_csrc[s0 + jj + 1];
            const float* xA = &xl_sh[srcA * Cn];
            const float* xB = &xl_sh[srcB * Cn];
            float vA0 = xA[lane] + xr0;       vA0 = (vA0 > 0.f) ? vA0 : 0.2f * vA0;
            float vB0 = xB[lane] + xr0;       vB0 = (vB0 > 0.f) ? vB0 : 0.2f * vB0;
            float vA1 = xA[lane + 32] + xr1;  vA1 = (vA1 > 0.f) ? vA1 : 0.2f * vA1;
            float vB1 = xB[lane + 32] + xr1;  vB1 = (vB1 > 0.f) ? vB1 : 0.2f * vB1;
            float vA2 = xA[lane + 64] + xr2;  vA2 = (vA2 > 0.f) ? vA2 : 0.2f * vA2;
            float vB2 = xB[lane + 64] + xr2;  vB2 = (vB2 > 0.f) ? vB2 : 0.2f * vB2;
            float sA = vA0 * attc0 + vA1 * attc1 + vA2 * attc2;
            float sB = vB0 * attc0 + vB1 * attc1 + vB2 * attc2;
            if (lane < 4) {
                float vA3 = xA[lane + 96] + xr3; vA3 = (vA3 > 0.f) ? vA3 : 0.2f * vA3;
                float vB3 = xB[lane + 96] + xr3; vB3 = (vB3 > 0.f) ? vB3 : 0.2f * vB3;
                sA += vA3 * attc3;
                sB += vB3 * attc3;
            }
            #pragma unroll
            for (int o = 16; o; o >>= 1) {
                sA += __shfl_xor_sync(0xffffffffu, sA, o);
                sB += __shfl_xor_sync(0xffffffffu, sB, o);
            }
            if (lane == 0) { lg_sh[s0 + jj] = sA; lg_sh[s0 + jj + 1] = sB; }
        }
        if (jj < len) {
            int src = g_csrc[s0 + jj];
            const float* x = &xl_sh[src * Cn];
            float v0 = x[lane] + xr0;       v0 = (v0 > 0.f) ? v0 : 0.2f * v0;
            float v1 = x[lane + 32] + xr1;  v1 = (v1 > 0.f) ? v1 : 0.2f * v1;
            float v2 = x[lane + 64] + xr2;  v2 = (v2 > 0.f) ? v2 : 0.2f * v2;
            float s = v0 * attc0 + v1 * attc1 + v2 * attc2;
            if (lane < 4) {
                float v3 = x[lane + 96] + xr3; v3 = (v3 > 0.f) ? v3 : 0.2f * v3;
                s += v3 * attc3;
            }
            #pragma unroll
            for (int o = 16; o; o >>= 1) s += __shfl_xor_sync(0xffffffffu, s, o);
            if (lane == 0) lg_sh[s0 + jj] = s;
        }
        __syncwarp();

        // ---- lane-parallel softmax over lg_sh[s0 .. s1) ----
        float mx = -1e30f;
        for (int off = lane; off < len; off += 32)
            mx = fmaxf(mx, lg_sh[s0 + off]);
        #pragma unroll
        for (int o = 16; o; o >>= 1) mx = fmaxf(mx, __shfl_xor_sync(0xffffffffu, mx, o));
        float den = 0.0f;
        for (int off = lane; off < len; off += 32) {
            float e = expf(lg_sh[s0 + off] - mx);
            lg_sh[s0 + off] = e;            // store unnormalized weight
            den += e;
        }
        #pragma unroll
        for (int o = 16; o; o >>= 1) den += __shfl_xor_sync(0xffffffffu, den, o);
        float inv = 1.0f / den;
        __syncwarp();

        // ---- pass 2: shuffle-free aggregation ----
        float a0 = 0, a1 = 0, a2 = 0, a3 = 0;
        for (int e2 = 0; e2 < len; e2++) {
            float al = lg_sh[s0 + e2] * inv;            // broadcast
            const float* x = &xl_sh[g_csrc[s0 + e2] * Cn];
            a0 += al * x[lane];
            a1 += al * x[lane + 32];
            a2 += al * x[lane + 64];
            if (lane < 4) a3 += al * x[lane + 96];
        }
        float* orow = g_gatout + ((size_t)b * Mn + t) * HC + h * Cn;
        orow[lane]      = a0 + bi0;
        orow[lane + 32] = a1 + bi1;
        orow[lane + 64] = a2 + bi2;
        if (lane < 4) orow[lane + 96] = a3 + bi3;
    }
}

// score[b][m] = tanh(gat_out[b,m,:]·pool_w / ||pool_w||)
__global__ void k_score(const float* __restrict__ pool_w)
{
    int gw = blockIdx.x * 8 + (threadIdx.x >> 5);
    int lane = threadIdx.x & 31;
    if (gw >= Bn * Mn) return;
    int b = gw / Mn, m = gw % Mn;
    const float* row = g_gatout + ((size_t)b * Mn + m) * HC;
    float nw = 0.0f, dt = 0.0f;
    for (int c = lane; c < HC; c += 32) {
        float w = pool_w[c];
        nw += w * w;
        dt += w * row[c];
    }
    #pragma unroll
    for (int o = 16; o; o >>= 1) {
        nw += __shfl_xor_sync(0xffffffffu, nw, o);
        dt += __shfl_xor_sync(0xffffffffu, dt, o);
    }
    if (lane == 0) g_score[b * Mn + m] = tanhf(dt / sqrtf(nw));
}

// top-k (K=160 of 200) by stable rank counting; write pooled into concat
__global__ void k_topk_pool()
{
    __shared__ float s_sh[Mn];
    __shared__ int   sel_idx[Kn];
    __shared__ float sel_val[Kn];
    int b = blockIdx.x;
    int tid = threadIdx.x;
    for (int i = tid; i < Mn; i += 256) s_sh[i] = g_score[b * Mn + i];
    __syncthreads();
    if (tid < Mn) {
        float sv = s_sh[tid];
        int rank = 0;
        for (int j = 0; j < Mn; j++) {
            float o = s_sh[j];
            rank += (o > sv) || (o == sv && j < tid);
        }
        if (rank < Kn) { sel_idx[rank] = tid; sel_val[rank] = sv; }
    }
    __syncthreads();
    for (int idx = tid; idx < Kn * HC; idx += 256) {
        int r = idx / HC, c = idx % HC;
        g_concat[b * D2IN + 100 + idx] =
            g_gatout[((size_t)b * Mn + sel_idx[r]) * HC + c] * sel_val[r];
    }
}

// ---------------- launch ----------------
extern "C" void kernel_launch(void* const* d_in, const int* in_sizes, int n_in,
                              void* d_out, int out_size)
{
    const float* obs    = (const float*)d_in[0];
    const float* past   = (const float*)d_in[1];
    const int*   ei     = (const int*)d_in[2];
    const float* d1_w   = (const float*)d_in[3];
    const float* d1_b   = (const float*)d_in[4];
    const float* d2_w   = (const float*)d_in[5];
    const float* d2_b   = (const float*)d_in[6];
    const float* gat_wl = (const float*)d_in[7];
    const float* gat_bl = (const float*)d_in[8];
    const float* gat_wr = (const float*)d_in[9];
    const float* gat_br = (const float*)d_in[10];
    const float* gat_att  = (const float*)d_in[11];
    const float* gat_bias = (const float*)d_in[12];
    const float* pool_w   = (const float*)d_in[13];
    const float* wih_f  = (const float*)d_in[14];
    const float* whh_f  = (const float*)d_in[15];
    const float* bih_f  = (const float*)d_in[16];
    const float* bhh_f  = (const float*)d_in[17];
    const float* wih_b  = (const float*)d_in[18];
    const float* whh_b  = (const float*)d_in[19];
    const float* bih_b  = (const float*)d_in[20];
    const float* bhh_b  = (const float*)d_in[21];
    const float* out_w  = (const float*)d_in[22];
    const float* out_b  = (const float*)d_in[23];
    float* out = (float*)d_out;

    float *p_xflat, *p_gx, *p_feat, *p_xl, *p_xr, *p_concat, *p_hidden;
    cudaGetSymbolAddress((void**)&p_xflat,  g_xflat);
    cudaGetSymbolAddress((void**)&p_gx,     g_gx);
    cudaGetSymbolAddress((void**)&p_feat,   g_feat);
    cudaGetSymbolAddress((void**)&p_xl,     g_xl);
    cudaGetSymbolAddress((void**)&p_xr,     g_xr);
    cudaGetSymbolAddress((void**)&p_concat, g_concat);
    cudaGetSymbolAddress((void**)&p_hidden, g_hidden);

    cudaFuncSetAttribute(k_gat_fused, cudaFuncAttributeMaxDynamicSharedMemorySize,
                         Mn * Cn * 4);

    // ---- GAT chain first (so the ncu capture window lands on big kernels) ----
    k_csr_count<<<1, 256>>>(ei);                                          // 0
    k_csr_scatter<<<(ETOT + 255) / 256, 256>>>(ei);                       // 1
    k_feat<<<(Bn * Mn * 42 + 255) / 256, 256>>>(obs);                     // 2
    gemm_dual<<<dim3(5, 400, 2), 256>>>(p_feat, 42, gat_wl, gat_wr, HC,   // 3
                                        p_xl, p_xr, HC, gat_bl, gat_br,
                                        Bn * Mn, HC, 42);
    k_gat_fused<<<dim3(Bn, Hn), 256, Mn * Cn * 4>>>(gat_att, gat_bias);   // 4
    k_score<<<(Bn * Mn + 7) / 8, 256>>>(pool_w);                          // 5
    k_topk_pool<<<Bn, 256>>>();                                           // 6

    // ---- LSTM input projection + recurrence ----
    k_xflat<<<(1280 * PASTD + 255) / 256, 256>>>(past);                   // 7
    gemm_bias_act<<<dim3(10, 10), 256>>>(p_xflat, PASTD, wih_f, GDIM,
                                         p_gx, GDIM, bih_f, bhh_f,
                                         640, GDIM, PASTD, 0, 0.0f);
    gemm_bias_act<<<dim3(10, 10), 256>>>(p_xflat + 640 * PASTD, PASTD, wih_b, GDIM,
                                         p_gx + 640 * GDIM, GDIM, bih_b, bhh_b,
                                         640, GDIM, PASTD, 0, 0.0f);
    for (int s = 0; s < Ln; s++) {
        k_gates<<<dim3(10, 4, 2), 256>>>(whh_f, whh_b, s);
        k_lstm_update<<<(2 * Bn * HIDn + 255) / 256, 256>>>(s);
    }

    // ---- d1 -> concat[:, 0:100] ----
    gemm_bias_act<<<dim3(2, 2), 256>>>(obs, OBSD, d1_w, 100,
                                       p_concat, D2IN, d1_b, nullptr,
                                       Bn, 100, 3 * Mn + 2, 1, 0.0f);

    // ---- d2 split-K GEMM (one 128x128 block per SM) + reduce/ELU ----
    gemm_splitk<<<SPLITK, 256>>>(p_concat, d2_w);
    k_d2_reduce_act<<<(Bn * 128 + 255) / 256, 256>>>(d2_b);

    // ---- output layer ----
    gemm_bias_act<<<dim3(4, 2), 256>>>(p_hidden, 128, out_w, Mn,
                                       out, Mn, out_b, nullptr,
                                       Bn, Mn, 128, 2, 0.01f);
}